// round 10
// baseline (speedup 1.0000x reference)
#include <cuda_runtime.h>
#include <cuda_bf16.h>
#include <math.h>

// Problem constants
#define BB 8
#define CC 128
#define HH 512
#define WW 512
#define HW (HH*WW)
#define KK 64
#define BK (BB*KK)      // 512 samples
#define NNEG 7
#define PP 4096
#define TAU 0.07f

// Fused-kernel structure
#define TQS 64
#define TPS 128
#define NQT (BK/TQS)    // 8
#define NPT (PP/TPS)    // 32
#define GATHER_BLOCKS 128              // 4 samples per block, 16 blocks per qt
#define SIM_BLOCKS (NQT*NPT)           // 256
#define GRID_MAIN (GATHER_BLOCKS + SIM_BLOCKS)  // 384

// Dynamic smem layout (bytes)
#define SM_Q 0                          // 64 rows x 512B (tf32, swizzled)
#define SM_P 32768                      // 128 rows x 512B
#define SM_PINV 98304                   // 128 floats
#define SMEM_TOTAL 98816

// Scratch (device globals; no allocation)
__device__ float g_qraw[BK*CC];
__device__ float g_qinv[BK];
__device__ float g_neglog[BK*NNEG];
__device__ unsigned long long g_best[BK];   // packed (mono(sim)<<32)|(~p)
__device__ unsigned int g_qt_done[NQT];     // gather stores visible
__device__ unsigned int g_neg_done[NQT];    // qinv+neglog visible
__device__ unsigned int g_qt_sim[NQT];      // sim blocks finished per qt
__device__ double g_qpart[NQT];
__device__ unsigned int g_fin;

__device__ __forceinline__ float dot4(float4 a, float4 b) {
    return a.x*b.x + a.y*b.y + a.z*b.z + a.w*b.w;
}

// monotone-ordered packing of (sim value, pool index); u64 max == argmax with
// smallest-index tie-break (first occurrence), order-independent.
__device__ __forceinline__ unsigned long long packmax(float v, int pg) {
    unsigned b = __float_as_uint(v);
    unsigned mono = (b & 0x80000000u) ? ~b : (b | 0x80000000u);
    return ((unsigned long long)mono << 32) | (unsigned)(0xFFFFFFFFu - pg);
}

__device__ __forceinline__ unsigned tf32c(float f) {
    unsigned r;
    asm("cvt.rna.tf32.f32 %0, %1;" : "=r"(r) : "f"(f));
    return r;
}

__device__ __forceinline__ unsigned smem_u32(const void* p) {
    unsigned r;
    asm("{ .reg .u64 t; cvta.to.shared.u64 t, %1; cvt.u32.u64 %0, t; }"
        : "=r"(r) : "l"(p));
    return r;
}

__device__ __forceinline__ void ldsm4(unsigned* d, unsigned addr) {
    asm volatile("ldmatrix.sync.aligned.m8n8.x4.shared.b16 {%0,%1,%2,%3}, [%4];"
        : "=r"(d[0]), "=r"(d[1]), "=r"(d[2]), "=r"(d[3]) : "r"(addr));
}
__device__ __forceinline__ void ldsm2(unsigned* d, unsigned addr) {
    asm volatile("ldmatrix.sync.aligned.m8n8.x2.shared.b16 {%0,%1}, [%2];"
        : "=r"(d[0]), "=r"(d[1]) : "r"(addr));
}
__device__ __forceinline__ void mma_tf32(float* c, const unsigned* a, const unsigned* b) {
    asm volatile(
        "mma.sync.aligned.m16n8k8.row.col.f32.tf32.tf32.f32 "
        "{%0,%1,%2,%3}, {%4,%5,%6,%7}, {%8,%9}, {%0,%1,%2,%3};"
        : "+f"(c[0]), "+f"(c[1]), "+f"(c[2]), "+f"(c[3])
        : "r"(a[0]), "r"(a[1]), "r"(a[2]), "r"(a[3]), "r"(b[0]), "r"(b[1]));
}

// ---------------------------------------------------------------------------
// K_MAIN (single fused kernel):
//   blocks 0..127:  gather (4 samples each, warp=sample, 4 loads/thread ->
//                   64K loads in flight across 128 SMs), flag qt_done EARLY,
//                   then qinv + negative logits, flag neg_done.
//   blocks 128..383: sim blocks. P tile + pool inv-norms overlap the gather,
//                   spin on qt_done, tf32 MMA, packed atomicMax argmax.
//                   LAST sim block per qt computes that qt's 64 losses;
//                   8th finalizer does the deterministic final sum -> out.
// ---------------------------------------------------------------------------
__global__ void __launch_bounds__(128, 2) k_main(const float* __restrict__ qf,
                                                 const float* __restrict__ pool,
                                                 const int* __restrict__ qidx,
                                                 const float* __restrict__ negs,
                                                 float* __restrict__ out) {
    extern __shared__ char sm[];
    const unsigned smb = smem_u32(sm);
    const int bid = blockIdx.x, tid = threadIdx.x;
    const int lane = tid & 31, wid = tid >> 5;

    if (bid < GATHER_BLOCKS) {
        // ---- Phase A: gather. block = 4 samples; warp = 1 sample;
        //      thread = 4 channels (c = lane + 32j). All loads independent.
        int qt = bid >> 4;
        int gq = bid * 4 + wid;
        int idx = qidx[gq];
        const float* base = qf + ((size_t)qt * CC) * HW + idx;
        float v[4];
#pragma unroll
        for (int j = 0; j < 4; j++)
            v[j] = __ldcs(base + (size_t)(lane + 32 * j) * HW);
#pragma unroll
        for (int j = 0; j < 4; j++)
            g_qraw[gq * CC + lane + 32 * j] = v[j];
        __threadfence();
        __syncthreads();
        if (tid == 0) atomicAdd(&g_qt_done[qt], 1u);   // unblock sim ASAP

        // ---- Phase B: per-sample inverse norm (from live registers).
        float ss = v[0]*v[0] + v[1]*v[1] + v[2]*v[2] + v[3]*v[3];
#pragma unroll
        for (int off = 16; off; off >>= 1)
            ss += __shfl_xor_sync(0xffffffffu, ss, off);
        float qinv = 1.0f / fmaxf(sqrtf(ss), 1e-12f);
        if (lane == 0) g_qinv[gq] = qinv;
        __syncthreads();   // qraw + qinv visible block-wide

        // ---- Phase C: negative logits. warp = its sample, 7 warp-wide dots.
        const float4* qrow = (const float4*)(g_qraw + (size_t)gq * CC);
        float4 qv = qrow[lane];
#pragma unroll
        for (int n = 0; n < NNEG; n++) {
            const float4* nrow = (const float4*)(negs + ((size_t)gq * NNEG + n) * CC);
            float4 nv = nrow[lane];
            float pd = dot4(qv, nv);
            float ns = dot4(nv, nv);
#pragma unroll
            for (int off = 16; off; off >>= 1) {
                pd += __shfl_xor_sync(0xffffffffu, pd, off);
                ns += __shfl_xor_sync(0xffffffffu, ns, off);
            }
            if (lane == 0)
                g_neglog[gq * NNEG + n] =
                    (pd * qinv / fmaxf(sqrtf(ns), 1e-12f)) / TAU;
        }
        __threadfence();
        __syncthreads();
        if (tid == 0) atomicAdd(&g_neg_done[qt], 1u);
        return;
    }

    // ---- sim block
    const int sb = bid - GATHER_BLOCKS;
    const int qt = sb >> 5, pt = sb & 31;
    const int qBase = qt * TQS, pBase = pt * TPS;

    // Phase 1: P tile global->smem, cvt to tf32, 32B-granule XOR swizzle.
    {
        const float4* psrc = (const float4*)(pool + (size_t)pBase * CC);
#pragma unroll
        for (int i = 0; i < 32; i++) {
            int e = tid + i * 128;           // 0..4095
            int r = e >> 5, kq = e & 31;
            float4 w = psrc[e];
            uint4 t = make_uint4(tf32c(w.x), tf32c(w.y), tf32c(w.z), tf32c(w.w));
            unsigned off = SM_P + r * 512 + ((((kq >> 1) ^ (r & 7))) << 5) + ((kq & 1) << 4);
            *((uint4*)(sm + off)) = t;
        }
    }
    __syncthreads();

    // Phase 2: pool inverse norms from smem.
    {
        int r = tid;
        float ss = 0.f;
#pragma unroll
        for (int kq = 0; kq < 32; kq++) {
            unsigned off = SM_P + r * 512 + ((((kq >> 1) ^ (r & 7))) << 5) + ((kq & 1) << 4);
            float4 w = *((const float4*)(sm + off));
            ss += dot4(w, w);
        }
        ((float*)(sm + SM_PINV))[r] = rsqrtf(fmaxf(ss, 1e-24f));
    }

    // Phase 3: wait for this qt's gather (16 producer blocks).
    if (tid == 0) {
        while (((volatile unsigned*)g_qt_done)[qt] < 16u) __nanosleep(64);
    }
    __syncthreads();
    __threadfence();

    // Phase 4: Q tile g_qraw->smem, cvt tf32, same swizzle.
    {
        const float4* qsrc = (const float4*)(g_qraw + (size_t)qBase * CC);
#pragma unroll
        for (int i = 0; i < 16; i++) {
            int e = tid + i * 128;           // 0..2047
            int r = e >> 5, kq = e & 31;
            float4 w = qsrc[e];
            uint4 t = make_uint4(tf32c(w.x), tf32c(w.y), tf32c(w.z), tf32c(w.w));
            unsigned off = SM_Q + r * 512 + ((((kq >> 1) ^ (r & 7))) << 5) + ((kq & 1) << 4);
            *((uint4*)(sm + off)) = t;
        }
    }
    __syncthreads();

    // Phase 5: mainloop. warp (qw, pw): 32q x 64p; m16n8k8 tf32.
    const int qw = wid & 1, pw = wid >> 1;
    const int x7 = lane & 7;
    unsigned Abase = smb + SM_Q + (unsigned)((qw * 32 + (lane & 15)) * 512) + ((lane >> 4) << 4);
    unsigned Amb1 = Abase + 16 * 512;
    unsigned Bbase[8];
#pragma unroll
    for (int nb = 0; nb < 8; nb++)
        Bbase[nb] = smb + SM_P + (unsigned)((pw * 64 + nb * 8 + (lane & 7)) * 512) + (((lane >> 3) & 1) << 4);

    float acc[2][8][4];
#pragma unroll
    for (int mb = 0; mb < 2; mb++)
#pragma unroll
        for (int nb = 0; nb < 8; nb++)
#pragma unroll
            for (int c = 0; c < 4; c++) acc[mb][nb][c] = 0.f;

#pragma unroll
    for (int ks = 0; ks < 16; ks++) {
        unsigned koff = (unsigned)((ks ^ x7) << 5);
        unsigned a0[4], a1[4];
        ldsm4(a0, Abase + koff);
        ldsm4(a1, Amb1 + koff);
#pragma unroll
        for (int nb = 0; nb < 8; nb++) {
            unsigned bb[2];
            ldsm2(bb, Bbase[nb] + koff);
            mma_tf32(acc[0][nb], a0, bb);
            mma_tf32(acc[1][nb], a1, bb);
        }
    }

    // Phase 6: epilogue — scale by pinv, pack, 4-lane merge, atomicMax.
    const float* s_pinv = (const float*)(sm + SM_PINV);
#pragma unroll
    for (int mb = 0; mb < 2; mb++) {
#pragma unroll
        for (int half = 0; half < 2; half++) {
            int q_blk = qw * 32 + mb * 16 + (lane >> 2) + half * 8;
            unsigned long long best = 0ULL;
#pragma unroll
            for (int nb = 0; nb < 8; nb++) {
#pragma unroll
                for (int c2 = 0; c2 < 2; c2++) {
                    int pl = pw * 64 + nb * 8 + (lane & 3) * 2 + c2;
                    float v = acc[mb][nb][half * 2 + c2] * s_pinv[pl];
                    unsigned long long pk = packmax(v, pBase + pl);
                    if (pk > best) best = pk;
                }
            }
#pragma unroll
            for (int off = 1; off < 4; off <<= 1) {
                unsigned long long ob = __shfl_xor_sync(0xffffffffu, best, off);
                if (ob > best) best = ob;
            }
            if ((lane & 3) == 0)
                atomicMax(&g_best[qBase + q_blk], best);
        }
    }

    // Phase 7: last sim block of this qt computes its 64 losses.
    __threadfence();           // order this block's atomicMax before counter
    __syncthreads();
    __shared__ int s_islast;
    if (tid == 0)
        s_islast = (atomicAdd(&g_qt_sim[qt], 1u) == (unsigned)(NPT - 1));
    __syncthreads();
    if (!s_islast) return;

    // wait for this qt's negative logits / qinv (normally long since done)
    if (tid == 0) {
        while (((volatile unsigned*)g_neg_done)[qt] < 16u) __nanosleep(64);
    }
    __syncthreads();
    __threadfence();

    float* s_lb = (float*)sm;            // reuse smem for 64 losses
    int grp = tid >> 3, gl = tid & 7;    // 16 8-lane groups
#pragma unroll
    for (int pass = 0; pass < 4; pass++) {
        int gq = qBase + pass * 16 + grp;
        unsigned long long pk = ((volatile unsigned long long*)g_best)[gq];
        int pstar = (int)(0xFFFFFFFFu - (unsigned)(pk & 0xFFFFFFFFu));
        const float4* qrow = (const float4*)(g_qraw + (size_t)gq * CC);
        const float4* prow = (const float4*)(pool + (size_t)pstar * CC);
        float d = 0.f, ps = 0.f;
#pragma unroll
        for (int k = 0; k < 4; k++) {
            float4 qv = qrow[gl + 8 * k];
            float4 pv = prow[gl + 8 * k];
            d  += dot4(qv, pv);
            ps += dot4(pv, pv);
        }
#pragma unroll
        for (int off = 1; off < 8; off <<= 1) {
            d  += __shfl_xor_sync(0xffffffffu, d, off);
            ps += __shfl_xor_sync(0xffffffffu, ps, off);
        }
        if (gl == 0) {
            g_best[gq] = 0ULL;   // reset for next graph replay
            float pinv = 1.0f / fmaxf(sqrtf(ps), 1e-12f);
            float l0 = (d * g_qinv[gq] * pinv) / TAU;
            float ln[NNEG];
#pragma unroll
            for (int n = 0; n < NNEG; n++) ln[n] = g_neglog[gq * NNEG + n];
            float m = l0;
#pragma unroll
            for (int n = 0; n < NNEG; n++) m = fmaxf(m, ln[n]);
            float se = expf(l0 - m);
#pragma unroll
            for (int n = 0; n < NNEG; n++) se += expf(ln[n] - m);
            s_lb[pass * 16 + grp] = logf(se) - (l0 - m);
        }
    }
    __syncthreads();

    if (tid == 0) {
        double part = 0.0;
#pragma unroll
        for (int i = 0; i < 64; i++) part += (double)s_lb[i];   // fixed order
        g_qpart[qt] = part;
        __threadfence();
        unsigned r = atomicAdd(&g_fin, 1u);
        if (r == (unsigned)(NQT - 1)) {          // global last finalizer
            __threadfence();
            double s = 0.0;
#pragma unroll
            for (int i = 0; i < NQT; i++)        // fixed order
                s += ((volatile double*)g_qpart)[i];
            out[0] = (float)(s / (double)BK);
            // reset cross-launch scratch for next graph replay
            g_fin = 0u;
#pragma unroll
            for (int i = 0; i < NQT; i++) {
                g_qt_done[i] = 0u;
                g_neg_done[i] = 0u;
                g_qt_sim[i] = 0u;
            }
        }
    }
}

// ---------------------------------------------------------------------------
extern "C" void kernel_launch(void* const* d_in, const int* in_sizes, int n_in,
                              void* d_out, int out_size) {
    const float* qf   = (const float*)d_in[0];   // [B,C,H,W]
    const float* pool = (const float*)d_in[1];   // [P,C]
    const float* negs = (const float*)d_in[2];   // [B,K,N,C]
    const int*   qidx = (const int*)d_in[3];     // [B,K]
    float* out = (float*)d_out;

    cudaFuncSetAttribute(k_main,
                         cudaFuncAttributeMaxDynamicSharedMemorySize, SMEM_TOTAL);

    k_main<<<GRID_MAIN, 128, SMEM_TOTAL>>>(qf, pool, qidx, negs, out);
}